// round 17
// baseline (speedup 1.0000x reference)
#include <cuda_runtime.h>
#include <cuda_fp16.h>
#include <math.h>
#include <stdint.h>

#define B_  4
#define S_  2048
#define D_  1024
#define H_  16
#define HD_ 64
#define NROW (B_*S_)          // 8192

#define TK      64
#define NCHUNK  (D_/TK)       // 16
#define TILE_B  16384         // bytes per 128-row x 128B tile (64 fp16 cols)

#define QSCALE 0.1803368801111601f   // 0.125 * log2(e)

// ---------------- scratch (static device globals; no allocation) ------------
__device__ __align__(128) __half g_x [NROW * D_];
__device__ __align__(128) __half g_c [NROW * D_];
__device__ __align__(128) __half g_wq[D_ * D_];
__device__ __align__(128) __half g_wk[D_ * D_];
__device__ __align__(128) __half g_wv[D_ * D_];
__device__ __align__(128) __half g_wo[D_ * D_];
__device__ __align__(128) __half g_q [NROW * D_];
__device__ __align__(128) __half g_k [NROW * D_];
__device__ __align__(128) __half g_v [NROW * D_];

// ---------------------------- helpers ---------------------------------------
__device__ __forceinline__ uint32_t smem_u32(const void* p) {
    uint32_t a;
    asm("{ .reg .u64 t; cvta.to.shared.u64 t, %1; cvt.u32.u64 %0, t; }"
        : "=r"(a) : "l"(p));
    return a;
}
__host__ __device__ __forceinline__ uint32_t swz128(uint32_t o) {
    return o ^ ((o >> 3) & 0x70);
}
__device__ __forceinline__ void cp16(uint32_t dst, const void* src) {
    asm volatile("cp.async.cg.shared.global [%0], [%1], 16;"
                 :: "r"(dst), "l"(src) : "memory");
}
__device__ __forceinline__ void cp_commit() {
    asm volatile("cp.async.commit_group;" ::: "memory");
}
template <int N>
__device__ __forceinline__ void cp_wait() {
    asm volatile("cp.async.wait_group %0;" :: "n"(N) : "memory");
}
__device__ __forceinline__ void ldm_x4(uint32_t* r, uint32_t addr) {
    asm volatile("ldmatrix.sync.aligned.m8n8.x4.shared.b16 {%0,%1,%2,%3}, [%4];"
                 : "=r"(r[0]), "=r"(r[1]), "=r"(r[2]), "=r"(r[3]) : "r"(addr));
}
__device__ __forceinline__ void ldm_x4t(uint32_t* r, uint32_t addr) {
    asm volatile("ldmatrix.sync.aligned.m8n8.x4.trans.shared.b16 {%0,%1,%2,%3}, [%4];"
                 : "=r"(r[0]), "=r"(r[1]), "=r"(r[2]), "=r"(r[3]) : "r"(addr));
}
__device__ __forceinline__ void mma16816(float* c, const uint32_t* a,
                                         const uint32_t* b) {
    asm volatile(
        "mma.sync.aligned.m16n8k16.row.col.f32.f16.f16.f32 "
        "{%0,%1,%2,%3}, {%4,%5,%6,%7}, {%8,%9}, {%0,%1,%2,%3};"
        : "+f"(c[0]), "+f"(c[1]), "+f"(c[2]), "+f"(c[3])
        : "r"(a[0]), "r"(a[1]), "r"(a[2]), "r"(a[3]), "r"(b[0]), "r"(b[1]));
}
__device__ __forceinline__ float ex2(float x) {
    float y;
    asm("ex2.approx.ftz.f32 %0, %1;" : "=f"(y) : "f"(x));
    return y;
}
__device__ __forceinline__ uint32_t pack2h(float a, float b) {
    __half2 h = __floats2half2_rn(a, b);
    return *reinterpret_cast<uint32_t*>(&h);
}

// ---------------------------------------------------------------------------
// Conversions: fp32 -> tiled/swizzled fp16 (unchanged)
// ---------------------------------------------------------------------------
__global__ __launch_bounds__(256) void conv_act(const float* __restrict__ in,
                                                __half* __restrict__ o)
{
    const int base = blockIdx.x * 256 + threadIdx.x;
#pragma unroll
    for (int jj = 0; jj < 2; jj++) {
        int idx = base + jj * 524288;
        int R  = idx >> 7, cb = idx & 127;
        int rb = R >> 7,  r  = R & 127;
        int kc = cb >> 3, cc = cb & 7;
        const float* p = in + (size_t)R * D_ + cb * 8;
        float4 a = *(const float4*)p;
        float4 b = *(const float4*)(p + 4);
        float v[8] = {a.x, a.y, a.z, a.w, b.x, b.y, b.z, b.w};
        union { __half h[8]; uint4 u; } uh;
#pragma unroll
        for (int j = 0; j < 8; j++) uh.h[j] = __float2half_rn(v[j]);
        uint32_t off = (uint32_t)(rb * NCHUNK + kc) * TILE_B + swz128(r * 128 + cc * 16);
        *(uint4*)((char*)o + off) = uh.u;
    }
}

__global__ __launch_bounds__(256) void conv_w4(
    const float* __restrict__ W0, const float* __restrict__ W1,
    const float* __restrict__ W2, const float* __restrict__ W3,
    __half* __restrict__ o0, __half* __restrict__ o1,
    __half* __restrict__ o2, __half* __restrict__ o3)
{
    const int wsel = blockIdx.y;
    const float* W = (wsel == 0) ? W0 : (wsel == 1) ? W1 : (wsel == 2) ? W2 : W3;
    __half* o = (wsel == 0) ? o0 : (wsel == 1) ? o1 : (wsel == 2) ? o2 : o3;

    int idx = blockIdx.x * 256 + threadIdx.x;
    int n  = idx & 1023, kb = idx >> 10;
    float v[8];
#pragma unroll
    for (int j = 0; j < 8; j++) v[j] = W[(size_t)(kb * 8 + j) * D_ + n];
    union { __half h[8]; uint4 u; } uh;
#pragma unroll
    for (int j = 0; j < 8; j++) uh.h[j] = __float2half_rn(v[j]);
    int tb = n >> 7, r = n & 127, kc = kb >> 3, cc = kb & 7;
    uint32_t off = (uint32_t)(tb * NCHUNK + kc) * TILE_B + swz128(r * 128 + cc * 16);
    *(uint4*)((char*)o + off) = uh.u;
}

// ---------------------------------------------------------------------------
// GEMM core — fp16, 4 warps (128 threads), warp tile 64x64 (2x fragment
// reuse vs 64x32), 2-stage double-buffered smem (2x32KB), occ=2.
// ---------------------------------------------------------------------------
#define GSTG      32768
#define GSM_BYTES (2 * GSTG)   // 65536

__device__ __forceinline__ void gemm_core(
    uint32_t S0, const char* gA, const char* gB,
    int tid, int wid, int lane, float acc[4][8][4])
{
    const int wm = wid >> 1, wn = wid & 1;
    const int a_row = wm * 64 + (lane & 15);
    const int a_cb0 = (lane >> 4) * 16;
    const int b_idx = lane >> 3;
    const int b_row = wn * 64 + ((b_idx >> 1) * 8) + (lane & 7);
    const int b_cb0 = (b_idx & 1) * 16;

    // prologue: chunk 0 -> stage 0
#pragma unroll
    for (int i = tid; i < 1024; i += 128) {
        cp16(S0 + i * 16,         gA + i * 16);
        cp16(S0 + 16384 + i * 16, gB + i * 16);
    }
    cp_commit();

    for (int c = 0; c < NCHUNK; c++) {
        if (c + 1 < NCHUNK) {
            const uint32_t st = S0 + (uint32_t)((c + 1) & 1) * GSTG;
            const uint32_t cofs = (uint32_t)(c + 1) * TILE_B;
#pragma unroll
            for (int i = tid; i < 1024; i += 128) {
                cp16(st + i * 16,         gA + cofs + i * 16);
                cp16(st + 16384 + i * 16, gB + cofs + i * 16);
            }
            cp_commit();
            cp_wait<1>();
        } else {
            cp_wait<0>();
        }
        __syncthreads();

        const uint32_t st = S0 + (uint32_t)(c & 1) * GSTG;
        const uint32_t SA = st, SB = st + 16384;

#pragma unroll
        for (int ks = 0; ks < 4; ks++) {
            uint32_t af[4][4], bf[8][2];
            const uint32_t acb = ks * 32 + a_cb0;
            const uint32_t bcb = ks * 32 + b_cb0;
#pragma unroll
            for (int i = 0; i < 4; i++)
                ldm_x4(af[i], SA + swz128((uint32_t)(a_row + i * 16) * 128 + acb));
#pragma unroll
            for (int jp = 0; jp < 4; jp++) {
                uint32_t t4[4];
                ldm_x4(t4, SB + swz128((uint32_t)(b_row + jp * 16) * 128 + bcb));
                bf[jp * 2 + 0][0] = t4[0]; bf[jp * 2 + 0][1] = t4[1];
                bf[jp * 2 + 1][0] = t4[2]; bf[jp * 2 + 1][1] = t4[3];
            }
#pragma unroll
            for (int i = 0; i < 4; i++)
#pragma unroll
                for (int j = 0; j < 8; j++) mma16816(acc[i][j], af[i], bf[j]);
        }
        __syncthreads();
    }
}

// Q/K/V in one launch
__global__ __launch_bounds__(128, 2) void gemm_qkv(
    const __half* __restrict__ A,
    const __half* __restrict__ wq, const __half* __restrict__ wk,
    const __half* __restrict__ wv,
    __half* __restrict__ q, __half* __restrict__ k, __half* __restrict__ v)
{
    extern __shared__ char sm[];
    const uint32_t S0 = smem_u32(sm);
    const int tid  = threadIdx.x;
    const int wid  = tid >> 5;
    const int lane = tid & 31;
    const int tb   = blockIdx.x;
    const int rb   = blockIdx.y;
    const int z    = blockIdx.z;

    const __half* Bm;
    __half* C;
    float osc;
    if (z == 0)      { Bm = wq; C = q; osc = QSCALE; }
    else if (z == 1) { Bm = wk; C = k; osc = 1.0f; }
    else             { Bm = wv; C = v; osc = 1.0f; }

    float acc[4][8][4];
#pragma unroll
    for (int i = 0; i < 4; i++)
#pragma unroll
        for (int j = 0; j < 8; j++)
#pragma unroll
            for (int r = 0; r < 4; r++) acc[i][j][r] = 0.f;

    gemm_core(S0,
              (const char*)A  + (size_t)rb * NCHUNK * TILE_B,
              (const char*)Bm + (size_t)tb * NCHUNK * TILE_B,
              tid, wid, lane, acc);

    const int wm = wid >> 1, wn = wid & 1;
    const int row0 = rb * 128 + wm * 64 + (lane >> 2);
    const int col0 = tb * 128 + wn * 64 + (lane & 3) * 2;
#pragma unroll
    for (int i = 0; i < 4; i++)
#pragma unroll
        for (int j = 0; j < 8; j++) {
            const int cc = col0 + j * 8;
            size_t p0 = ((size_t)(row0 + i * 16) * D_ + cc) * 2;
            size_t p1 = ((size_t)(row0 + i * 16 + 8) * D_ + cc) * 2;
            *(uint32_t*)((char*)C + p0) = pack2h(acc[i][j][0] * osc, acc[i][j][1] * osc);
            *(uint32_t*)((char*)C + p1) = pack2h(acc[i][j][2] * osc, acc[i][j][3] * osc);
        }
}

// output projection: fp32 epilogue + bias
__global__ __launch_bounds__(128, 2) void gemm_out(
    const __half* __restrict__ A, const __half* __restrict__ Bm,
    const float* __restrict__ bias, float* __restrict__ C)
{
    extern __shared__ char sm[];
    const uint32_t S0 = smem_u32(sm);
    const int tid  = threadIdx.x;
    const int wid  = tid >> 5;
    const int lane = tid & 31;
    const int tb   = blockIdx.x;
    const int rb   = blockIdx.y;

    float acc[4][8][4];
#pragma unroll
    for (int i = 0; i < 4; i++)
#pragma unroll
        for (int j = 0; j < 8; j++)
#pragma unroll
            for (int r = 0; r < 4; r++) acc[i][j][r] = 0.f;

    gemm_core(S0,
              (const char*)A  + (size_t)rb * NCHUNK * TILE_B,
              (const char*)Bm + (size_t)tb * NCHUNK * TILE_B,
              tid, wid, lane, acc);

    const int wm = wid >> 1, wn = wid & 1;
    const int row0 = rb * 128 + wm * 64 + (lane >> 2);
    const int col0 = tb * 128 + wn * 64 + (lane & 3) * 2;
#pragma unroll
    for (int i = 0; i < 4; i++)
#pragma unroll
        for (int j = 0; j < 8; j++) {
            const int cc = col0 + j * 8;
            const float b0 = bias[cc], b1 = bias[cc + 1];
            float* p0 = C + (size_t)(row0 + i * 16) * D_ + cc;
            float* p1 = C + (size_t)(row0 + i * 16 + 8) * D_ + cc;
            *(float2*)p0 = make_float2(acc[i][j][0] + b0, acc[i][j][1] + b1);
            *(float2*)p1 = make_float2(acc[i][j][2] + b0, acc[i][j][3] + b1);
        }
}

// ---------------------------------------------------------------------------
// Flash attention — 4 warps (128 threads), warp covers 32 q-rows (2 m16
// slabs): K/V fragment duplication halved vs 8x16-row warps.
// smem: Q 16KB + 2 stages x (K 8KB + V 8KB) = 48KB; occ=2.
// ---------------------------------------------------------------------------
#define FSMEM (16384 + 32768)

__device__ __forceinline__ void fa_load_stage(
    uint32_t sst, int st, int jb, int tid, size_t rowoff_base,
    const __half* k, const __half* v)
{
    const int r  = tid >> 1;          // 0..63
    const int u0 = (tid & 1) * 4;     // 0 or 4
    const size_t rowoff = rowoff_base + (size_t)(jb * 64 + r) * 2048;
    const uint32_t base = sst + st * 16384;
    const char* s0 = (const char*)k + rowoff;
    const char* s1 = (const char*)v + rowoff;
#pragma unroll
    for (int uu = 0; uu < 4; uu++) {
        const uint32_t d = swz128(r * 128 + (u0 + uu) * 16);
        const int sb = (u0 + uu) * 16;
        cp16(base + d,        s0 + sb);
        cp16(base + 8192 + d, s1 + sb);
    }
}

__global__ __launch_bounds__(128, 2) void flash_mma(
    const __half* __restrict__ q, const __half* __restrict__ k,
    const __half* __restrict__ v, __half* __restrict__ ctx)
{
    extern __shared__ char sm[];
    const uint32_t SQ  = smem_u32(sm);
    const uint32_t SST = SQ + 16384;

    const int tid  = threadIdx.x;
    const int w    = tid >> 5;        // 0..3
    const int lane = tid & 31;
    const int qb   = 15 - blockIdx.x;
    const int h    = blockIdx.y;
    const int b    = blockIdx.z;
    const int qbase = qb * 128;
    const size_t seqoff = ((size_t)b * 2048) * 2048 + (size_t)h * 128;  // bytes

    // Q tile: 128 rows x 128B, one row per thread
    {
        const int r = tid;
        const size_t ro = seqoff + (size_t)(qbase + r) * 2048;
        const char* s = (const char*)q + ro;
#pragma unroll
        for (int u = 0; u < 8; u++)
            cp16(SQ + swz128(r * 128 + u * 16), s + u * 16);
    }
    cp_commit();

    const int nkb = 2 * qb + 2;
    fa_load_stage(SST, 0, 0, tid, seqoff, k, v);
    cp_commit();
    cp_wait<0>();
    __syncthreads();

    // Q fragments: 2 slabs x 4 kt
    uint32_t aq[2][4][4];
    {
        const int acb = (lane >> 4) * 16;
#pragma unroll
        for (int s = 0; s < 2; s++) {
            const int ar = w * 32 + s * 16 + (lane & 15);
#pragma unroll
            for (int kt = 0; kt < 4; kt++)
                ldm_x4(aq[s][kt], SQ + swz128((uint32_t)ar * 128 + kt * 32 + acb));
        }
    }

    float o[2][8][4];
#pragma unroll
    for (int s = 0; s < 2; s++)
#pragma unroll
        for (int n = 0; n < 8; n++)
#pragma unroll
            for (int r = 0; r < 4; r++) o[s][n][r] = 0.f;
    float m0[2] = {-INFINITY, -INFINITY}, m1[2] = {-INFINITY, -INFINITY};
    float l0[2] = {0.f, 0.f}, l1[2] = {0.f, 0.f};

    const int wrow0 = qbase + w * 32;   // warp's lowest q row

    for (int jb = 0; jb < nkb; jb++) {
        if (jb + 1 < nkb) {
            fa_load_stage(SST, (jb + 1) & 1, jb + 1, tid, seqoff, k, v);
            cp_commit();
            cp_wait<1>();
        } else {
            cp_wait<0>();
        }
        __syncthreads();

        const int kbase = jb * 64;
        if (kbase <= wrow0 + 31) {
            const uint32_t base = SST + (uint32_t)(jb & 1) * 16384;
            const uint32_t KH = base, VH = base + 8192;

            float sacc[2][8][4];
#pragma unroll
            for (int s = 0; s < 2; s++)
#pragma unroll
                for (int n = 0; n < 8; n++)
#pragma unroll
                    for (int r = 0; r < 4; r++) sacc[s][n][r] = 0.f;

            const uint32_t krow = ((lane >> 4) & 1) * 8 + (lane & 7);
            const uint32_t kcb  = ((lane >> 3) & 1) * 16;
#pragma unroll
            for (int kt = 0; kt < 4; kt++) {
#pragma unroll
                for (int ntp = 0; ntp < 4; ntp++) {
                    uint32_t b4[4];
                    ldm_x4(b4, KH + swz128((ntp * 16 + krow) * 128 + kt * 32 + kcb));
#pragma unroll
                    for (int s = 0; s < 2; s++) {
                        mma16816(sacc[s][2 * ntp],     aq[s][kt], b4 + 0);
                        mma16816(sacc[s][2 * ntp + 1], aq[s][kt], b4 + 2);
                    }
                }
            }

            // causal mask (near diagonal only)
            if (kbase + 63 > wrow0) {
#pragma unroll
                for (int s = 0; s < 2; s++) {
                    const int rg = wrow0 + s * 16 + (lane >> 2);
#pragma unroll
                    for (int nt = 0; nt < 8; nt++) {
                        const int cg = kbase + nt * 8 + (lane & 3) * 2;
                        if (cg     > rg)     sacc[s][nt][0] = -INFINITY;
                        if (cg + 1 > rg)     sacc[s][nt][1] = -INFINITY;
                        if (cg     > rg + 8) sacc[s][nt][2] = -INFINITY;
                        if (cg + 1 > rg + 8) sacc[s][nt][3] = -INFINITY;
                    }
                }
            }

            // online softmax per slab (log2 domain; scale folded into Q)
            uint32_t ph[2][4][4];
#pragma unroll
            for (int s = 0; s < 2; s++) {
                float nm0 = m0[s], nm1 = m1[s];
#pragma unroll
                for (int nt = 0; nt < 8; nt++) {
                    nm0 = fmaxf(nm0, fmaxf(sacc[s][nt][0], sacc[s][nt][1]));
                    nm1 = fmaxf(nm1, fmaxf(sacc[s][nt][2], sacc[s][nt][3]));
                }
                nm0 = fmaxf(nm0, __shfl_xor_sync(0xffffffffu, nm0, 1));
                nm0 = fmaxf(nm0, __shfl_xor_sync(0xffffffffu, nm0, 2));
                nm1 = fmaxf(nm1, __shfl_xor_sync(0xffffffffu, nm1, 1));
                nm1 = fmaxf(nm1, __shfl_xor_sync(0xffffffffu, nm1, 2));

                const float sc0 = ex2(m0[s] - nm0);
                const float sc1 = ex2(m1[s] - nm1);
                m0[s] = nm0; m1[s] = nm1;
                l0[s] *= sc0; l1[s] *= sc1;
#pragma unroll
                for (int nt = 0; nt < 8; nt++) {
                    o[s][nt][0] *= sc0; o[s][nt][1] *= sc0;
                    o[s][nt][2] *= sc1; o[s][nt][3] *= sc1;
                }

                float rs0 = 0.f, rs1 = 0.f;
#pragma unroll
                for (int t = 0; t < 4; t++) {
#pragma unroll
                    for (int hh = 0; hh < 2; hh++) {
                        const int nt = 2 * t + hh;
                        const float p0 = ex2(sacc[s][nt][0] - nm0);
                        const float p1 = ex2(sacc[s][nt][1] - nm0);
                        const float p2 = ex2(sacc[s][nt][2] - nm1);
                        const float p3 = ex2(sacc[s][nt][3] - nm1);
                        rs0 += p0 + p1; rs1 += p2 + p3;
                        ph[s][t][2 * hh + 0] = pack2h(p0, p1);
                        ph[s][t][2 * hh + 1] = pack2h(p2, p3);
                    }
                }
                rs0 += __shfl_xor_sync(0xffffffffu, rs0, 1);
                rs0 += __shfl_xor_sync(0xffffffffu, rs0, 2);
                rs1 += __shfl_xor_sync(0xffffffffu, rs1, 1);
                rs1 += __shfl_xor_sync(0xffffffffu, rs1, 2);
                l0[s] += rs0; l1[s] += rs1;
            }

            // O += P V
            const uint32_t vrow = lane & 15;
            const uint32_t vcg  = lane >> 4;
#pragma unroll
            for (int kt = 0; kt < 4; kt++) {
#pragma unroll
                for (int ntp = 0; ntp < 4; ntp++) {
                    uint32_t b4[4];
                    ldm_x4t(b4, VH + swz128((kt * 16 + vrow) * 128 + (2 * ntp + vcg) * 16));
#pragma unroll
                    for (int s = 0; s < 2; s++) {
                        mma16816(o[s][2 * ntp],     ph[s][kt], b4 + 0);
                        mma16816(o[s][2 * ntp + 1], ph[s][kt], b4 + 2);
                    }
                }
            }
        }
        __syncthreads();
    }

    // normalize; write ctx in tiled/swizzled fp16 for gemm_out
    const int rb_t = b * 16 + qb;
    const uint32_t tbase = (uint32_t)(rb_t * NCHUNK + h) * TILE_B;
#pragma unroll
    for (int s = 0; s < 2; s++) {
        const float i0 = 1.f / l0[s];
        const float i1 = 1.f / l1[s];
        const int rl0 = w * 32 + s * 16 + (lane >> 2);
#pragma unroll
        for (int nt = 0; nt < 8; nt++) {
            const int col2 = (nt * 8 + (lane & 3) * 2) * 2;
            uint32_t off = tbase + swz128((uint32_t)rl0 * 128 + col2);
            *(uint32_t*)((char*)ctx + off) = pack2h(o[s][nt][0] * i0, o[s][nt][1] * i0);
            off = tbase + swz128((uint32_t)(rl0 + 8) * 128 + col2);
            *(uint32_t*)((char*)ctx + off) = pack2h(o[s][nt][2] * i1, o[s][nt][3] * i1);
        }
    }
}

// ---------------------------------------------------------------------------
extern "C" void kernel_launch(void* const* d_in, const int* in_sizes, int n_in,
                              void* d_out, int out_size)
{
    const float* x  = (const float*)d_in[0];
    const float* Wq = (const float*)d_in[1];
    const float* Wk = (const float*)d_in[2];
    const float* Wv = (const float*)d_in[3];
    const float* Wo = (const float*)d_in[4];
    const float* bo = (const float*)d_in[5];
    float* out = (float*)d_out;

    __half *xh, *ch, *wq, *wk, *wv, *wo, *q, *k, *v;
    cudaGetSymbolAddress((void**)&xh, g_x);
    cudaGetSymbolAddress((void**)&ch, g_c);
    cudaGetSymbolAddress((void**)&wq, g_wq);
    cudaGetSymbolAddress((void**)&wk, g_wk);
    cudaGetSymbolAddress((void**)&wv, g_wv);
    cudaGetSymbolAddress((void**)&wo, g_wo);
    cudaGetSymbolAddress((void**)&q,  g_q);
    cudaGetSymbolAddress((void**)&k,  g_k);
    cudaGetSymbolAddress((void**)&v,  g_v);

    cudaFuncSetAttribute(gemm_qkv, cudaFuncAttributeMaxDynamicSharedMemorySize,
                         GSM_BYTES);
    cudaFuncSetAttribute(gemm_out, cudaFuncAttributeMaxDynamicSharedMemorySize,
                         GSM_BYTES);
    cudaFuncSetAttribute(flash_mma, cudaFuncAttributeMaxDynamicSharedMemorySize,
                         FSMEM);

    conv_act<<<2048, 256>>>(x, xh);
    dim3 wg(512, 4);
    conv_w4<<<wg, 256>>>(Wq, Wk, Wv, Wo, wq, wk, wv, wo);

    dim3 gq(D_ / 128, NROW / 128, 3);   // (8, 64, 3)
    gemm_qkv<<<gq, 128, GSM_BYTES>>>(xh, wq, wk, wv, q, k, v);

    dim3 fg(S_ / 128, H_, B_);          // (16, 16, 4)
    flash_mma<<<fg, 128, FSMEM>>>(q, k, v, ch);

    dim3 gg(D_ / 128, NROW / 128);      // (8, 64)
    gemm_out<<<gg, 128, GSM_BYTES>>>(ch, wo, bo, out);
}